// round 2
// baseline (speedup 1.0000x reference)
#include <cuda_runtime.h>
#include <math.h>
#include <stdint.h>

// Problem shape (fixed by the dataset)
#define NG 16384   // n_genes  (rows of Q / output)
#define NL 4096    // n_latent (rows of K, softmax axis)
#define DK 64      // d_k
#define NC 1024    // n_cells  (cols of V / output)
#define OUT_ELEMS (NG * NC)            // 16,777,216

// ---------------------------------------------------------------------------
// JAX threefry2x32 Gumbel noise, *partitionable* mode (default in modern JAX):
// for flat element i (row-major over (NG, NL)):
//   counter = uint64(i) -> (hi, lo) = (0, i) since i < 2^32
//   (o0, o1) = threefry2x32(key=(0,42), x=(hi, lo))
//   bits     = o0 ^ o1
//   u = max(tiny, bitcast(0x3F800000 | bits>>9) - 1 + tiny)   (== f, or tiny if f==0)
//   g = -log(-log(u))
// ---------------------------------------------------------------------------
__device__ __forceinline__ float gumbel_at(uint32_t e) {
    uint32_t x0 = 0u;          // counts_hi + ks0 (=0)
    uint32_t x1 = e;
    const uint32_t ks1 = 42u;
    const uint32_t ks2 = 0x1BD11BDAu ^ 42u;   // ks0 ^ ks1 ^ 0x1BD11BDA, ks0 = 0
    // initial key injection (ks0 = 0)
    x1 += ks1;
#define TFR(r) { x0 += x1; x1 = __funnelshift_l(x1, x1, (r)); x1 ^= x0; }
    TFR(13) TFR(15) TFR(26) TFR(6)
    x0 += ks1; x1 += ks2 + 1u;
    TFR(17) TFR(29) TFR(16) TFR(24)
    x0 += ks2; x1 += 2u;              // + ks0 (=0) + 2
    TFR(13) TFR(15) TFR(26) TFR(6)
    /* x0 += ks0 (=0) */ x1 += ks1 + 3u;
    TFR(17) TFR(29) TFR(16) TFR(24)
    x0 += ks1; x1 += ks2 + 4u;
    TFR(13) TFR(15) TFR(26) TFR(6)
    x0 += ks2; x1 += 5u;              // + ks0 (=0) + 5
#undef TFR
    uint32_t bits = x0 ^ x1;          // partitionable 32-bit fold
    // u in [tiny, 1): f = bitcast(1.0 | mantissa) - 1.0 is exact; f-1 is exact.
    float f = __uint_as_float(0x3F800000u | (bits >> 9)) - 1.0f;
    // w = -log(u).  log1pf(f-1) is accurate even for f near 1 (f-1 exact).
    // f == 0  ->  u = tiny = 2^-126  ->  w = 126*ln2.
    float w = (f > 0.0f) ? (-log1pf(f - 1.0f)) : 87.33654475f;
    return -logf(w);
}

// ---------------------------------------------------------------------------
// Kernel A: S = (Q @ K^T) / 8 + gumbel  ->  written into p_attn region
// M=NG, N=NL, K=DK. Both operands row-major [*, 64] ("NT" gemm).
// 128x128 block tile, 256 threads, 8x8 microtile, k-chunk 16.
// ---------------------------------------------------------------------------
__global__ __launch_bounds__(256)
void score_kernel(const float* __restrict__ Q, const float* __restrict__ Km,
                  float* __restrict__ S)
{
    __shared__ float As[16][132];   // [k][m], padded: conflict-free
    __shared__ float Bs[16][132];   // [k][n]
    const int bm = blockIdx.y, bn = blockIdx.x;
    const int tid = threadIdx.x;
    const int tx = tid & 15, ty = tid >> 4;

    float acc[8][8];
#pragma unroll
    for (int i = 0; i < 8; i++)
#pragma unroll
        for (int j = 0; j < 8; j++) acc[i][j] = 0.0f;

    for (int k0 = 0; k0 < DK; k0 += 16) {
#pragma unroll
        for (int p = 0; p < 2; p++) {
            int idx = tid * 2 + p;          // 0..511 -> 128 rows x 4 float4
            int row = idx >> 2;
            int c4  = idx & 3;
            float4 va = *(const float4*)(Q  + (size_t)(bm * 128 + row) * DK + k0 + c4 * 4);
            As[c4 * 4 + 0][row] = va.x; As[c4 * 4 + 1][row] = va.y;
            As[c4 * 4 + 2][row] = va.z; As[c4 * 4 + 3][row] = va.w;
            float4 vb = *(const float4*)(Km + (size_t)(bn * 128 + row) * DK + k0 + c4 * 4);
            Bs[c4 * 4 + 0][row] = vb.x; Bs[c4 * 4 + 1][row] = vb.y;
            Bs[c4 * 4 + 2][row] = vb.z; Bs[c4 * 4 + 3][row] = vb.w;
        }
        __syncthreads();
#pragma unroll
        for (int kk = 0; kk < 16; kk++) {
            float a[8], b[8];
            *(float4*)&a[0] = *(const float4*)&As[kk][ty * 8];
            *(float4*)&a[4] = *(const float4*)&As[kk][ty * 8 + 4];
            *(float4*)&b[0] = *(const float4*)&Bs[kk][tx * 8];
            *(float4*)&b[4] = *(const float4*)&Bs[kk][tx * 8 + 4];
#pragma unroll
            for (int i = 0; i < 8; i++)
#pragma unroll
                for (int j = 0; j < 8; j++)
                    acc[i][j] = fmaf(a[i], b[j], acc[i][j]);
        }
        __syncthreads();
    }

#pragma unroll
    for (int i = 0; i < 8; i++) {
        uint32_t m = bm * 128 + ty * 8 + i;
#pragma unroll
        for (int j = 0; j < 8; j++) {
            uint32_t n = bn * 128 + tx * 8 + j;
            uint32_t e = m * (uint32_t)NL + n;
            S[e] = acc[i][j] * 0.125f + gumbel_at(e);
        }
    }
}

// ---------------------------------------------------------------------------
// Kernel B: in-place row softmax over NL=4096 (one block per row).
// Row cached in smem: 1 global read, 1 global write, 1 expf per element.
// ---------------------------------------------------------------------------
__global__ __launch_bounds__(256)
void softmax_kernel(float* __restrict__ P)
{
    __shared__ float4 row4[NL / 4];   // 16 KB
    __shared__ float red[8];
    const int r = blockIdx.x, t = threadIdx.x;
    float4* g = (float4*)(P + (size_t)r * NL);

    float mx = -INFINITY;
#pragma unroll
    for (int q = 0; q < 4; q++) {
        float4 v = g[t + 256 * q];
        row4[t + 256 * q] = v;
        mx = fmaxf(mx, fmaxf(fmaxf(v.x, v.y), fmaxf(v.z, v.w)));
    }
#pragma unroll
    for (int o = 16; o > 0; o >>= 1)
        mx = fmaxf(mx, __shfl_xor_sync(0xffffffffu, mx, o));
    if ((t & 31) == 0) red[t >> 5] = mx;
    __syncthreads();
    mx = red[0];
#pragma unroll
    for (int w = 1; w < 8; w++) mx = fmaxf(mx, red[w]);
    __syncthreads();   // everyone done reading red before reuse

    float s = 0.0f;
#pragma unroll
    for (int q = 0; q < 4; q++) {
        float4 v = row4[t + 256 * q];
        v.x = expf(v.x - mx); v.y = expf(v.y - mx);
        v.z = expf(v.z - mx); v.w = expf(v.w - mx);
        row4[t + 256 * q] = v;
        s += (v.x + v.y) + (v.z + v.w);
    }
#pragma unroll
    for (int o = 16; o > 0; o >>= 1)
        s += __shfl_xor_sync(0xffffffffu, s, o);
    if ((t & 31) == 0) red[t >> 5] = s;
    __syncthreads();
    float tot = red[0];
#pragma unroll
    for (int w = 1; w < 8; w++) tot += red[w];
    float inv = 1.0f / tot;
    __syncthreads();

#pragma unroll
    for (int q = 0; q < 4; q++) {
        float4 v = row4[t + 256 * q];
        v.x *= inv; v.y *= inv; v.z *= inv; v.w *= inv;
        g[t + 256 * q] = v;
    }
}

// ---------------------------------------------------------------------------
// Kernel C: out = P @ V.  M=NG, N=NC, K=NL ("NN" gemm).
// Same 128x128 / 8x8 structure, k-chunk 16 over K=4096.
// ---------------------------------------------------------------------------
__global__ __launch_bounds__(256)
void out_kernel(const float* __restrict__ P, const float* __restrict__ V,
                float* __restrict__ O)
{
    __shared__ float As[16][132];   // P chunk, transposed [k][m]
    __shared__ float Bs[16][132];   // V chunk, direct     [k][n]
    const int bm = blockIdx.y, bn = blockIdx.x;
    const int tid = threadIdx.x;
    const int tx = tid & 15, ty = tid >> 4;

    float acc[8][8];
#pragma unroll
    for (int i = 0; i < 8; i++)
#pragma unroll
        for (int j = 0; j < 8; j++) acc[i][j] = 0.0f;

    for (int k0 = 0; k0 < NL; k0 += 16) {
#pragma unroll
        for (int p = 0; p < 2; p++) {
            int idx = tid * 2 + p;          // 0..511
            // P: 128 rows x 16 k  (transpose into As)
            int row = idx >> 2;
            int c4  = idx & 3;
            float4 va = *(const float4*)(P + (size_t)(bm * 128 + row) * NL + k0 + c4 * 4);
            As[c4 * 4 + 0][row] = va.x; As[c4 * 4 + 1][row] = va.y;
            As[c4 * 4 + 2][row] = va.z; As[c4 * 4 + 3][row] = va.w;
            // V: 16 k-rows x 128 n  (direct into Bs)
            int brow = idx >> 5;            // 0..15
            int bc4  = idx & 31;            // 0..31
            float4 vb = *(const float4*)(V + (size_t)(k0 + brow) * NC + bn * 128 + bc4 * 4);
            *(float4*)&Bs[brow][bc4 * 4] = vb;
        }
        __syncthreads();
#pragma unroll
        for (int kk = 0; kk < 16; kk++) {
            float a[8], b[8];
            *(float4*)&a[0] = *(const float4*)&As[kk][ty * 8];
            *(float4*)&a[4] = *(const float4*)&As[kk][ty * 8 + 4];
            *(float4*)&b[0] = *(const float4*)&Bs[kk][tx * 8];
            *(float4*)&b[4] = *(const float4*)&Bs[kk][tx * 8 + 4];
#pragma unroll
            for (int i = 0; i < 8; i++)
#pragma unroll
                for (int j = 0; j < 8; j++)
                    acc[i][j] = fmaf(a[i], b[j], acc[i][j]);
        }
        __syncthreads();
    }

#pragma unroll
    for (int i = 0; i < 8; i++) {
        size_t m = bm * 128 + ty * 8 + i;
        float* dst = O + m * NC + bn * 128 + tx * 8;
        *(float4*)(dst)     = *(float4*)&acc[i][0];
        *(float4*)(dst + 4) = *(float4*)&acc[i][4];
    }
}

// ---------------------------------------------------------------------------
// Launch: scores+gumbel -> in-place softmax -> P @ V.
// p_attn lives directly in its slice of d_out (no scratch needed).
// ---------------------------------------------------------------------------
extern "C" void kernel_launch(void* const* d_in, const int* in_sizes, int n_in,
                              void* d_out, int out_size) {
    const float* Q  = (const float*)d_in[0];   // [16384, 64]
    const float* Km = (const float*)d_in[1];   // [4096, 64]
    const float* V  = (const float*)d_in[2];   // [4096, 1024]
    float* out = (float*)d_out;                // [16384, 1024]
    float* P   = out + OUT_ELEMS;              // [16384, 4096] (p_attn output slice)

    dim3 gA(NL / 128, NG / 128);               // 32 x 128
    score_kernel<<<gA, 256>>>(Q, Km, P);

    softmax_kernel<<<NG, 256>>>(P);

    dim3 gC(NC / 128, NG / 128);               // 8 x 128
    out_kernel<<<gC, 256>>>(P, V, out);
}

// round 4
// speedup vs baseline: 1.7081x; 1.7081x over previous
#include <cuda_runtime.h>
#include <cuda_bf16.h>
#include <math.h>
#include <stdint.h>

// Problem shape (fixed by the dataset)
#define NG 16384   // n_genes
#define NL 4096    // n_latent (softmax axis, GEMM-K)
#define DK 64      // d_k
#define NC 1024    // n_cells
#define OUT_ELEMS (NG * NC)

// ---------------------------------------------------------------------------
// bf16 hi/lo scratch (static device arrays: allocation-free scratch)
// ---------------------------------------------------------------------------
__device__ __nv_bfloat16 g_Phi[(size_t)NG * NL];   // 134 MB
__device__ __nv_bfloat16 g_Plo[(size_t)NG * NL];   // 134 MB
__device__ __nv_bfloat16 g_VhiT[(size_t)NC * NL];  // 8 MB   V^T hi  [n][k]
__device__ __nv_bfloat16 g_VloT[(size_t)NC * NL];  // 8 MB   V^T lo  [n][k]

__device__ __forceinline__ uint32_t smem_to_u32(const void* p) {
    uint32_t a;
    asm("{ .reg .u64 t; cvta.to.shared.u64 t, %1; cvt.u32.u64 %0, t; }" : "=r"(a) : "l"(p));
    return a;
}

// ---------------------------------------------------------------------------
// JAX threefry2x32 Gumbel noise, partitionable mode, key (0, 42)
// ---------------------------------------------------------------------------
__device__ __forceinline__ float gumbel_at(uint32_t e) {
    uint32_t x0 = 0u, x1 = e;
    const uint32_t ks1 = 42u;
    const uint32_t ks2 = 0x1BD11BDAu ^ 42u;
    x1 += ks1;
#define TFR(r) { x0 += x1; x1 = __funnelshift_l(x1, x1, (r)); x1 ^= x0; }
    TFR(13) TFR(15) TFR(26) TFR(6)
    x0 += ks1; x1 += ks2 + 1u;
    TFR(17) TFR(29) TFR(16) TFR(24)
    x0 += ks2; x1 += 2u;
    TFR(13) TFR(15) TFR(26) TFR(6)
    x1 += ks1 + 3u;
    TFR(17) TFR(29) TFR(16) TFR(24)
    x0 += ks1; x1 += ks2 + 4u;
    TFR(13) TFR(15) TFR(26) TFR(6)
    x0 += ks2; x1 += 5u;
#undef TFR
    uint32_t bits = x0 ^ x1;
    float f = __uint_as_float(0x3F800000u | (bits >> 9)) - 1.0f;
    float w = (f > 0.0f) ? (-log1pf(f - 1.0f)) : 87.33654475f;
    return -logf(w);
}

// ---------------------------------------------------------------------------
// Kernel A: S = (Q @ K^T)/8 + gumbel
// ---------------------------------------------------------------------------
__global__ __launch_bounds__(256)
void score_kernel(const float* __restrict__ Q, const float* __restrict__ Km,
                  float* __restrict__ S)
{
    __shared__ float As[16][132];
    __shared__ float Bs[16][132];
    const int bm = blockIdx.y, bn = blockIdx.x;
    const int tid = threadIdx.x;
    const int tx = tid & 15, ty = tid >> 4;

    float acc[8][8];
#pragma unroll
    for (int i = 0; i < 8; i++)
#pragma unroll
        for (int j = 0; j < 8; j++) acc[i][j] = 0.0f;

    for (int k0 = 0; k0 < DK; k0 += 16) {
#pragma unroll
        for (int p = 0; p < 2; p++) {
            int idx = tid * 2 + p;
            int row = idx >> 2;
            int c4  = idx & 3;
            float4 va = *(const float4*)(Q  + (size_t)(bm * 128 + row) * DK + k0 + c4 * 4);
            As[c4 * 4 + 0][row] = va.x; As[c4 * 4 + 1][row] = va.y;
            As[c4 * 4 + 2][row] = va.z; As[c4 * 4 + 3][row] = va.w;
            float4 vb = *(const float4*)(Km + (size_t)(bn * 128 + row) * DK + k0 + c4 * 4);
            Bs[c4 * 4 + 0][row] = vb.x; Bs[c4 * 4 + 1][row] = vb.y;
            Bs[c4 * 4 + 2][row] = vb.z; Bs[c4 * 4 + 3][row] = vb.w;
        }
        __syncthreads();
#pragma unroll
        for (int kk = 0; kk < 16; kk++) {
            float a[8], b[8];
            *(float4*)&a[0] = *(const float4*)&As[kk][ty * 8];
            *(float4*)&a[4] = *(const float4*)&As[kk][ty * 8 + 4];
            *(float4*)&b[0] = *(const float4*)&Bs[kk][tx * 8];
            *(float4*)&b[4] = *(const float4*)&Bs[kk][tx * 8 + 4];
#pragma unroll
            for (int i = 0; i < 8; i++)
#pragma unroll
                for (int j = 0; j < 8; j++)
                    acc[i][j] = fmaf(a[i], b[j], acc[i][j]);
        }
        __syncthreads();
    }

#pragma unroll
    for (int i = 0; i < 8; i++) {
        uint32_t m = bm * 128 + ty * 8 + i;
#pragma unroll
        for (int j = 0; j < 8; j++) {
            uint32_t n = bn * 128 + tx * 8 + j;
            uint32_t e = m * (uint32_t)NL + n;
            S[e] = acc[i][j] * 0.125f + gumbel_at(e);
        }
    }
}

// ---------------------------------------------------------------------------
// Kernel B: in-place row softmax + fused bf16 hi/lo split of P
// ---------------------------------------------------------------------------
__device__ __forceinline__ void split1(float x, __nv_bfloat16& h, __nv_bfloat16& l) {
    h = __float2bfloat16(x);
    l = __float2bfloat16(x - __bfloat162float(h));
}

__global__ __launch_bounds__(256)
void softmax_kernel(float* __restrict__ P)
{
    __shared__ float4 row4[NL / 4];
    __shared__ float red[8];
    const int r = blockIdx.x, t = threadIdx.x;
    float4* g = (float4*)(P + (size_t)r * NL);

    float mx = -INFINITY;
#pragma unroll
    for (int q = 0; q < 4; q++) {
        float4 v = g[t + 256 * q];
        row4[t + 256 * q] = v;
        mx = fmaxf(mx, fmaxf(fmaxf(v.x, v.y), fmaxf(v.z, v.w)));
    }
#pragma unroll
    for (int o = 16; o > 0; o >>= 1)
        mx = fmaxf(mx, __shfl_xor_sync(0xffffffffu, mx, o));
    if ((t & 31) == 0) red[t >> 5] = mx;
    __syncthreads();
    mx = red[0];
#pragma unroll
    for (int w = 1; w < 8; w++) mx = fmaxf(mx, red[w]);
    __syncthreads();

    float s = 0.0f;
#pragma unroll
    for (int q = 0; q < 4; q++) {
        float4 v = row4[t + 256 * q];
        v.x = expf(v.x - mx); v.y = expf(v.y - mx);
        v.z = expf(v.z - mx); v.w = expf(v.w - mx);
        row4[t + 256 * q] = v;
        s += (v.x + v.y) + (v.z + v.w);
    }
#pragma unroll
    for (int o = 16; o > 0; o >>= 1)
        s += __shfl_xor_sync(0xffffffffu, s, o);
    if ((t & 31) == 0) red[t >> 5] = s;
    __syncthreads();
    float tot = red[0];
#pragma unroll
    for (int w = 1; w < 8; w++) tot += red[w];
    float inv = 1.0f / tot;
    __syncthreads();

    uint2* ph = (uint2*)(g_Phi + (size_t)r * NL);
    uint2* pl = (uint2*)(g_Plo + (size_t)r * NL);
#pragma unroll
    for (int q = 0; q < 4; q++) {
        float4 v = row4[t + 256 * q];
        v.x *= inv; v.y *= inv; v.z *= inv; v.w *= inv;
        g[t + 256 * q] = v;
        __nv_bfloat16 hx, hy, hz, hw, lx, ly, lz, lw;
        split1(v.x, hx, lx); split1(v.y, hy, ly);
        split1(v.z, hz, lz); split1(v.w, hw, lw);
        __nv_bfloat162 h01 = __nv_bfloat162(hx, hy), h23 = __nv_bfloat162(hz, hw);
        __nv_bfloat162 l01 = __nv_bfloat162(lx, ly), l23 = __nv_bfloat162(lz, lw);
        uint2 hv, lv;
        hv.x = *(uint32_t*)&h01; hv.y = *(uint32_t*)&h23;
        lv.x = *(uint32_t*)&l01; lv.y = *(uint32_t*)&l23;
        ph[t + 256 * q] = hv;
        pl[t + 256 * q] = lv;
    }
}

// ---------------------------------------------------------------------------
// Kernel B2: transpose + bf16-split V:  V[k][n] -> V^T hi/lo [n][k]
// ---------------------------------------------------------------------------
__global__ __launch_bounds__(256)
void vsplit_kernel(const float* __restrict__ V)
{
    __shared__ float tile[32][33];
    const int n0 = blockIdx.x * 32, k0 = blockIdx.y * 32;
    const int tx = threadIdx.x & 31, ty = threadIdx.x >> 5;   // 32 x 8
#pragma unroll
    for (int i = 0; i < 32; i += 8)
        tile[ty + i][tx] = V[(size_t)(k0 + ty + i) * NC + n0 + tx];
    __syncthreads();
#pragma unroll
    for (int i = 0; i < 32; i += 8) {
        float f = tile[tx][ty + i];            // = V[k0+tx][n0+ty+i]
        __nv_bfloat16 h, l;
        split1(f, h, l);
        size_t o = (size_t)(n0 + ty + i) * NL + k0 + tx;
        g_VhiT[o] = h;
        g_VloT[o] = l;
    }
}

// ---------------------------------------------------------------------------
// Kernel C: out = P @ V via warp-level bf16 mma.sync (baseline PTX, no tcgen05)
// 3 products: Phi*Vhi + Phi*Vlo + Plo*Vhi, fp32 accum.
// CTA tile 128x128, 8 warps (2x4), warp tile 64x32, BK=32.
// ---------------------------------------------------------------------------
#define SP 40   // smem row stride in bf16 (80B): conflict-free for ldmatrix

__device__ __forceinline__ void ldsm4(uint32_t* r, uint32_t addr) {
    asm volatile("ldmatrix.sync.aligned.m8n8.x4.shared.b16 {%0,%1,%2,%3}, [%4];"
                 : "=r"(r[0]), "=r"(r[1]), "=r"(r[2]), "=r"(r[3]) : "r"(addr));
}
__device__ __forceinline__ void mma_bf16(float* c, const uint32_t* a,
                                         uint32_t b0, uint32_t b1) {
    asm volatile("mma.sync.aligned.m16n8k16.row.col.f32.bf16.bf16.f32 "
                 "{%0,%1,%2,%3}, {%4,%5,%6,%7}, {%8,%9}, {%0,%1,%2,%3};"
                 : "+f"(c[0]), "+f"(c[1]), "+f"(c[2]), "+f"(c[3])
                 : "r"(a[0]), "r"(a[1]), "r"(a[2]), "r"(a[3]), "r"(b0), "r"(b1));
}

__global__ __launch_bounds__(256, 2)
void pv_kernel(float* __restrict__ O)
{
    __shared__ __align__(16) uint16_t sPhi[128 * SP];
    __shared__ __align__(16) uint16_t sPlo[128 * SP];
    __shared__ __align__(16) uint16_t sVhi[128 * SP];
    __shared__ __align__(16) uint16_t sVlo[128 * SP];

    const int tid = threadIdx.x;
    const int lane = tid & 31, wid = tid >> 5;
    const int wm = wid >> 2, wn = wid & 3;           // warp grid 2 x 4
    const int bn = blockIdx.x, bm = blockIdx.y;

    const __nv_bfloat16* pPhi = g_Phi  + (size_t)(bm * 128) * NL;
    const __nv_bfloat16* pPlo = g_Plo  + (size_t)(bm * 128) * NL;
    const __nv_bfloat16* pVhi = g_VhiT + (size_t)(bn * 128) * NL;
    const __nv_bfloat16* pVlo = g_VloT + (size_t)(bn * 128) * NL;

    float acc[4][4][4];
#pragma unroll
    for (int i = 0; i < 4; i++)
#pragma unroll
        for (int j = 0; j < 4; j++)
#pragma unroll
            for (int q = 0; q < 4; q++) acc[i][j][q] = 0.0f;

    // ldmatrix lane address pattern (identical formula for A and B tiles)
    const int lrow = (lane & 7) + ((lane >> 3) & 1) * 8;   // 0..15
    const int lcol8 = (lane >> 4) * 8;                     // 0 or 8
    const uint32_t uPhi = smem_to_u32(sPhi), uPlo = smem_to_u32(sPlo);
    const uint32_t uVhi = smem_to_u32(sVhi), uVlo = smem_to_u32(sVlo);

    for (int k0 = 0; k0 < NL; k0 += 32) {
        __syncthreads();   // previous iteration's reads done
#pragma unroll
        for (int u = 0; u < 2; u++) {
            int idx = tid + 256 * u;           // 0..511 -> 128 rows x 4 k-chunks
            int row = idx >> 2, kc = idx & 3;
            size_t go = (size_t)row * NL + k0 + kc * 8;
            uint32_t so = row * SP + kc * 8;   // bf16 units
            *(uint4*)&sPhi[so] = *(const uint4*)(pPhi + go);
            *(uint4*)&sPlo[so] = *(const uint4*)(pPlo + go);
            *(uint4*)&sVhi[so] = *(const uint4*)(pVhi + go);
            *(uint4*)&sVlo[so] = *(const uint4*)(pVlo + go);
        }
        __syncthreads();

#pragma unroll
        for (int kk = 0; kk < 32; kk += 16) {
            const uint32_t aoff = ((wm * 64 + lrow) * SP + kk + lcol8) * 2;
            const uint32_t boff = ((wn * 32 + lrow) * SP + kk + lcol8) * 2;
            uint32_t ah[4][4], al[4][4];
#pragma unroll
            for (int mt = 0; mt < 4; mt++) {
                ldsm4(ah[mt], uPhi + aoff + mt * (16 * SP * 2));
                ldsm4(al[mt], uPlo + aoff + mt * (16 * SP * 2));
            }
            uint32_t bh[2][4], bl[2][4];
#pragma unroll
            for (int np = 0; np < 2; np++) {
                ldsm4(bh[np], uVhi + boff + np * (16 * SP * 2));
                ldsm4(bl[np], uVlo + boff + np * (16 * SP * 2));
            }
#pragma unroll
            for (int mt = 0; mt < 4; mt++)
#pragma unroll
                for (int nt = 0; nt < 4; nt++) {
                    const int np = nt >> 1, sel = nt & 1;
                    mma_bf16(acc[mt][nt], ah[mt], bh[np][sel], bh[np][sel + 2]);
                    mma_bf16(acc[mt][nt], ah[mt], bl[np][sel], bl[np][sel + 2]);
                    mma_bf16(acc[mt][nt], al[mt], bh[np][sel], bh[np][sel + 2]);
                }
        }
    }

    // Epilogue: c0,c1 -> (m, col..col+1); c2,c3 -> (m+8, col..col+1)
#pragma unroll
    for (int mt = 0; mt < 4; mt++) {
        int m = bm * 128 + wm * 64 + mt * 16 + (lane >> 2);
#pragma unroll
        for (int nt = 0; nt < 4; nt++) {
            int col = bn * 128 + wn * 32 + nt * 8 + 2 * (lane & 3);
            float2 v0 = make_float2(acc[mt][nt][0], acc[mt][nt][1]);
            float2 v1 = make_float2(acc[mt][nt][2], acc[mt][nt][3]);
            *(float2*)(O + (size_t)m * NC + col)       = v0;
            *(float2*)(O + (size_t)(m + 8) * NC + col) = v1;
        }
    }
}

// ---------------------------------------------------------------------------
// Launch
// ---------------------------------------------------------------------------
extern "C" void kernel_launch(void* const* d_in, const int* in_sizes, int n_in,
                              void* d_out, int out_size) {
    const float* Q  = (const float*)d_in[0];   // [16384, 64]
    const float* Km = (const float*)d_in[1];   // [4096, 64]
    const float* V  = (const float*)d_in[2];   // [4096, 1024]
    float* out = (float*)d_out;                // [16384, 1024]
    float* P   = out + OUT_ELEMS;              // [16384, 4096] p_attn

    dim3 gA(NL / 128, NG / 128);
    score_kernel<<<gA, 256>>>(Q, Km, P);

    vsplit_kernel<<<dim3(NC / 32, NL / 32), 256>>>(V);

    softmax_kernel<<<NG, 256>>>(P);

    dim3 gC(NC / 128, NG / 128);               // 8 x 128
    pv_kernel<<<gC, 256>>>(out);
}

// round 5
// speedup vs baseline: 2.1154x; 1.2385x over previous
#include <cuda_runtime.h>
#include <cuda_bf16.h>
#include <math.h>
#include <stdint.h>

// Problem shape (fixed by the dataset)
#define NG 16384   // n_genes
#define NL 4096    // n_latent (softmax axis, GEMM-K)
#define DK 64      // d_k
#define NC 1024    // n_cells
#define OUT_ELEMS (NG * NC)

// ---------------------------------------------------------------------------
// bf16 hi/lo scratch (static device arrays: allocation-free scratch)
// ---------------------------------------------------------------------------
__device__ __nv_bfloat16 g_Phi[(size_t)NG * NL];   // 134 MB
__device__ __nv_bfloat16 g_Plo[(size_t)NG * NL];   // 134 MB
__device__ __nv_bfloat16 g_VhiT[(size_t)NC * NL];  // 8 MB   V^T hi  [n][k]
__device__ __nv_bfloat16 g_VloT[(size_t)NC * NL];  // 8 MB   V^T lo  [n][k]

__device__ __forceinline__ uint32_t smem_to_u32(const void* p) {
    uint32_t a;
    asm("{ .reg .u64 t; cvta.to.shared.u64 t, %1; cvt.u32.u64 %0, t; }" : "=r"(a) : "l"(p));
    return a;
}

// ---------------------------------------------------------------------------
// JAX threefry2x32 Gumbel noise, partitionable mode, key (0, 42)
// ---------------------------------------------------------------------------
__device__ __forceinline__ float gumbel_at(uint32_t e) {
    uint32_t x0 = 0u, x1 = e;
    const uint32_t ks1 = 42u;
    const uint32_t ks2 = 0x1BD11BDAu ^ 42u;
    x1 += ks1;
#define TFR(r) { x0 += x1; x1 = __funnelshift_l(x1, x1, (r)); x1 ^= x0; }
    TFR(13) TFR(15) TFR(26) TFR(6)
    x0 += ks1; x1 += ks2 + 1u;
    TFR(17) TFR(29) TFR(16) TFR(24)
    x0 += ks2; x1 += 2u;
    TFR(13) TFR(15) TFR(26) TFR(6)
    x1 += ks1 + 3u;
    TFR(17) TFR(29) TFR(16) TFR(24)
    x0 += ks1; x1 += ks2 + 4u;
    TFR(13) TFR(15) TFR(26) TFR(6)
    x0 += ks2; x1 += 5u;
#undef TFR
    uint32_t bits = x0 ^ x1;
    float f = __uint_as_float(0x3F800000u | (bits >> 9)) - 1.0f;
    // inner log must be high precision near u ~ 1 (f-1 exact -> log1pf)
    float w = (f > 0.0f) ? (-log1pf(f - 1.0f)) : 87.33654475f;
    // outer log: MUFU-based fast log is plenty accurate (2e-7 relative)
    return -__logf(w);
}

// ---------------------------------------------------------------------------
// Kernel A: S = (Q @ K^T)/8 + gumbel
// ---------------------------------------------------------------------------
__global__ __launch_bounds__(256)
void score_kernel(const float* __restrict__ Q, const float* __restrict__ Km,
                  float* __restrict__ S)
{
    __shared__ float As[16][132];
    __shared__ float Bs[16][132];
    const int bm = blockIdx.y, bn = blockIdx.x;
    const int tid = threadIdx.x;
    const int tx = tid & 15, ty = tid >> 4;

    float acc[8][8];
#pragma unroll
    for (int i = 0; i < 8; i++)
#pragma unroll
        for (int j = 0; j < 8; j++) acc[i][j] = 0.0f;

    for (int k0 = 0; k0 < DK; k0 += 16) {
#pragma unroll
        for (int p = 0; p < 2; p++) {
            int idx = tid * 2 + p;
            int row = idx >> 2;
            int c4  = idx & 3;
            float4 va = *(const float4*)(Q  + (size_t)(bm * 128 + row) * DK + k0 + c4 * 4);
            As[c4 * 4 + 0][row] = va.x; As[c4 * 4 + 1][row] = va.y;
            As[c4 * 4 + 2][row] = va.z; As[c4 * 4 + 3][row] = va.w;
            float4 vb = *(const float4*)(Km + (size_t)(bn * 128 + row) * DK + k0 + c4 * 4);
            Bs[c4 * 4 + 0][row] = vb.x; Bs[c4 * 4 + 1][row] = vb.y;
            Bs[c4 * 4 + 2][row] = vb.z; Bs[c4 * 4 + 3][row] = vb.w;
        }
        __syncthreads();
#pragma unroll
        for (int kk = 0; kk < 16; kk++) {
            float a[8], b[8];
            *(float4*)&a[0] = *(const float4*)&As[kk][ty * 8];
            *(float4*)&a[4] = *(const float4*)&As[kk][ty * 8 + 4];
            *(float4*)&b[0] = *(const float4*)&Bs[kk][tx * 8];
            *(float4*)&b[4] = *(const float4*)&Bs[kk][tx * 8 + 4];
#pragma unroll
            for (int i = 0; i < 8; i++)
#pragma unroll
                for (int j = 0; j < 8; j++)
                    acc[i][j] = fmaf(a[i], b[j], acc[i][j]);
        }
        __syncthreads();
    }

#pragma unroll
    for (int i = 0; i < 8; i++) {
        uint32_t m = bm * 128 + ty * 8 + i;
        uint32_t e0 = m * (uint32_t)NL + bn * 128 + tx * 8;
        float4 o0, o1;
        o0.x = acc[i][0] * 0.125f + gumbel_at(e0 + 0);
        o0.y = acc[i][1] * 0.125f + gumbel_at(e0 + 1);
        o0.z = acc[i][2] * 0.125f + gumbel_at(e0 + 2);
        o0.w = acc[i][3] * 0.125f + gumbel_at(e0 + 3);
        o1.x = acc[i][4] * 0.125f + gumbel_at(e0 + 4);
        o1.y = acc[i][5] * 0.125f + gumbel_at(e0 + 5);
        o1.z = acc[i][6] * 0.125f + gumbel_at(e0 + 6);
        o1.w = acc[i][7] * 0.125f + gumbel_at(e0 + 7);
        *(float4*)(S + e0)     = o0;
        *(float4*)(S + e0 + 4) = o1;
    }
}

// ---------------------------------------------------------------------------
// Kernel B: in-place row softmax + fused bf16 hi/lo split of P
// ---------------------------------------------------------------------------
__device__ __forceinline__ void split1(float x, __nv_bfloat16& h, __nv_bfloat16& l) {
    h = __float2bfloat16(x);
    l = __float2bfloat16(x - __bfloat162float(h));
}

__global__ __launch_bounds__(256)
void softmax_kernel(float* __restrict__ P)
{
    __shared__ float4 row4[NL / 4];
    __shared__ float red[8];
    const int r = blockIdx.x, t = threadIdx.x;
    float4* g = (float4*)(P + (size_t)r * NL);

    float mx = -INFINITY;
#pragma unroll
    for (int q = 0; q < 4; q++) {
        float4 v = g[t + 256 * q];
        row4[t + 256 * q] = v;
        mx = fmaxf(mx, fmaxf(fmaxf(v.x, v.y), fmaxf(v.z, v.w)));
    }
#pragma unroll
    for (int o = 16; o > 0; o >>= 1)
        mx = fmaxf(mx, __shfl_xor_sync(0xffffffffu, mx, o));
    if ((t & 31) == 0) red[t >> 5] = mx;
    __syncthreads();
    mx = red[0];
#pragma unroll
    for (int w = 1; w < 8; w++) mx = fmaxf(mx, red[w]);
    __syncthreads();

    float s = 0.0f;
#pragma unroll
    for (int q = 0; q < 4; q++) {
        float4 v = row4[t + 256 * q];
        v.x = __expf(v.x - mx); v.y = __expf(v.y - mx);
        v.z = __expf(v.z - mx); v.w = __expf(v.w - mx);
        row4[t + 256 * q] = v;
        s += (v.x + v.y) + (v.z + v.w);
    }
#pragma unroll
    for (int o = 16; o > 0; o >>= 1)
        s += __shfl_xor_sync(0xffffffffu, s, o);
    if ((t & 31) == 0) red[t >> 5] = s;
    __syncthreads();
    float tot = red[0];
#pragma unroll
    for (int w = 1; w < 8; w++) tot += red[w];
    float inv = 1.0f / tot;
    __syncthreads();

    uint2* ph = (uint2*)(g_Phi + (size_t)r * NL);
    uint2* pl = (uint2*)(g_Plo + (size_t)r * NL);
#pragma unroll
    for (int q = 0; q < 4; q++) {
        float4 v = row4[t + 256 * q];
        v.x *= inv; v.y *= inv; v.z *= inv; v.w *= inv;
        g[t + 256 * q] = v;
        __nv_bfloat16 hx, hy, hz, hw, lx, ly, lz, lw;
        split1(v.x, hx, lx); split1(v.y, hy, ly);
        split1(v.z, hz, lz); split1(v.w, hw, lw);
        __nv_bfloat162 h01 = __nv_bfloat162(hx, hy), h23 = __nv_bfloat162(hz, hw);
        __nv_bfloat162 l01 = __nv_bfloat162(lx, ly), l23 = __nv_bfloat162(lz, lw);
        uint2 hv, lv;
        hv.x = *(uint32_t*)&h01; hv.y = *(uint32_t*)&h23;
        lv.x = *(uint32_t*)&l01; lv.y = *(uint32_t*)&l23;
        ph[t + 256 * q] = hv;
        pl[t + 256 * q] = lv;
    }
}

// ---------------------------------------------------------------------------
// Kernel B2: transpose + bf16-split V:  V[k][n] -> V^T hi/lo [n][k]
// ---------------------------------------------------------------------------
__global__ __launch_bounds__(256)
void vsplit_kernel(const float* __restrict__ V)
{
    __shared__ float tile[32][33];
    const int n0 = blockIdx.x * 32, k0 = blockIdx.y * 32;
    const int tx = threadIdx.x & 31, ty = threadIdx.x >> 5;   // 32 x 8
#pragma unroll
    for (int i = 0; i < 32; i += 8)
        tile[ty + i][tx] = V[(size_t)(k0 + ty + i) * NC + n0 + tx];
    __syncthreads();
#pragma unroll
    for (int i = 0; i < 32; i += 8) {
        float f = tile[tx][ty + i];            // = V[k0+tx][n0+ty+i]
        __nv_bfloat16 h, l;
        split1(f, h, l);
        size_t o = (size_t)(n0 + ty + i) * NL + k0 + tx;
        g_VhiT[o] = h;
        g_VloT[o] = l;
    }
}

// ---------------------------------------------------------------------------
// Kernel C: out = P @ V via warp-level bf16 mma.sync, cp.async double-buffered
// 3 products: Phi*Vhi + Phi*Vlo + Plo*Vhi, fp32 accum.
// CTA tile 128x128, 8 warps (2x4), warp tile 64x32, BK=32, 2 stages.
// ---------------------------------------------------------------------------
#define SP 40                     // smem row stride in bf16 (80B)
#define ARR_BYTES (128 * SP * 2)  // 10240 B per array per stage
#define STAGE_BYTES (4 * ARR_BYTES)
#define PV_SMEM (2 * STAGE_BYTES) // 81920 B

__device__ __forceinline__ void ldsm4(uint32_t* r, uint32_t addr) {
    asm volatile("ldmatrix.sync.aligned.m8n8.x4.shared.b16 {%0,%1,%2,%3}, [%4];"
                 : "=r"(r[0]), "=r"(r[1]), "=r"(r[2]), "=r"(r[3]) : "r"(addr));
}
__device__ __forceinline__ void mma_bf16(float* c, const uint32_t* a,
                                         uint32_t b0, uint32_t b1) {
    asm volatile("mma.sync.aligned.m16n8k16.row.col.f32.bf16.bf16.f32 "
                 "{%0,%1,%2,%3}, {%4,%5,%6,%7}, {%8,%9}, {%0,%1,%2,%3};"
                 : "+f"(c[0]), "+f"(c[1]), "+f"(c[2]), "+f"(c[3])
                 : "r"(a[0]), "r"(a[1]), "r"(a[2]), "r"(a[3]), "r"(b0), "r"(b1));
}
__device__ __forceinline__ void cpa16(uint32_t dst, const void* src) {
    asm volatile("cp.async.cg.shared.global [%0], [%1], 16;" :: "r"(dst), "l"(src));
}
#define CP_COMMIT() asm volatile("cp.async.commit_group;" ::: "memory")
#define CP_WAIT1()  asm volatile("cp.async.wait_group 1;" ::: "memory")
#define CP_WAIT0()  asm volatile("cp.async.wait_group 0;" ::: "memory")

__global__ __launch_bounds__(256, 2)
void pv_kernel(float* __restrict__ O)
{
    extern __shared__ __align__(16) char dsm[];
    const uint32_t sbase = smem_to_u32(dsm);

    const int tid = threadIdx.x;
    const int lane = tid & 31, wid = tid >> 5;
    const int wm = wid >> 2, wn = wid & 3;           // warp grid 2 x 4
    const int bn = blockIdx.x, bm = blockIdx.y;

    const __nv_bfloat16* srcs[4] = {
        g_Phi  + (size_t)(bm * 128) * NL,
        g_Plo  + (size_t)(bm * 128) * NL,
        g_VhiT + (size_t)(bn * 128) * NL,
        g_VloT + (size_t)(bn * 128) * NL
    };

    float acc[4][4][4];
#pragma unroll
    for (int i = 0; i < 4; i++)
#pragma unroll
        for (int j = 0; j < 4; j++)
#pragma unroll
            for (int q = 0; q < 4; q++) acc[i][j][q] = 0.0f;

    const int lrow = (lane & 7) + ((lane >> 3) & 1) * 8;   // 0..15
    const int lcol8 = (lane >> 4) * 8;                     // 0 or 8

    // --- async load of one 32-K stage (8 x cp.async 16B per thread) ---
    auto load_stage = [&](int st, int k0) {
        uint32_t stb = sbase + st * STAGE_BYTES;
#pragma unroll
        for (int a = 0; a < 4; a++)
#pragma unroll
            for (int u = 0; u < 2; u++) {
                int idx = tid + 256 * u;           // 0..511: 128 rows x 4 kc
                int row = idx >> 2, kc = idx & 3;
                uint32_t dst = stb + a * ARR_BYTES + (row * SP + kc * 8) * 2;
                cpa16(dst, srcs[a] + (size_t)row * NL + k0 + kc * 8);
            }
    };

    load_stage(0, 0);
    CP_COMMIT();

    const int NCH = NL / 32;   // 128 chunks
    for (int c = 0; c < NCH; c++) {
        if (c + 1 < NCH) {
            load_stage((c + 1) & 1, (c + 1) * 32);
            CP_COMMIT();
            CP_WAIT1();
        } else {
            CP_WAIT0();
        }
        __syncthreads();

        const uint32_t stb = sbase + (c & 1) * STAGE_BYTES;
        const uint32_t uPhi = stb, uPlo = stb + ARR_BYTES;
        const uint32_t uVhi = stb + 2 * ARR_BYTES, uVlo = stb + 3 * ARR_BYTES;

#pragma unroll
        for (int kk = 0; kk < 32; kk += 16) {
            const uint32_t aoff = ((wm * 64 + lrow) * SP + kk + lcol8) * 2;
            const uint32_t boff = ((wn * 32 + lrow) * SP + kk + lcol8) * 2;
            uint32_t ah[4][4], al[4][4];
#pragma unroll
            for (int mt = 0; mt < 4; mt++) {
                ldsm4(ah[mt], uPhi + aoff + mt * (16 * SP * 2));
                ldsm4(al[mt], uPlo + aoff + mt * (16 * SP * 2));
            }
            uint32_t bh[2][4], bl[2][4];
#pragma unroll
            for (int np = 0; np < 2; np++) {
                ldsm4(bh[np], uVhi + boff + np * (16 * SP * 2));
                ldsm4(bl[np], uVlo + boff + np * (16 * SP * 2));
            }
#pragma unroll
            for (int mt = 0; mt < 4; mt++)
#pragma unroll
                for (int nt = 0; nt < 4; nt++) {
                    const int np = nt >> 1, sel = nt & 1;
                    mma_bf16(acc[mt][nt], ah[mt], bh[np][sel], bh[np][sel + 2]);
                    mma_bf16(acc[mt][nt], ah[mt], bl[np][sel], bl[np][sel + 2]);
                    mma_bf16(acc[mt][nt], al[mt], bh[np][sel], bh[np][sel + 2]);
                }
        }
        __syncthreads();
    }

    // Epilogue
#pragma unroll
    for (int mt = 0; mt < 4; mt++) {
        int m = bm * 128 + wm * 64 + mt * 16 + (lane >> 2);
#pragma unroll
        for (int nt = 0; nt < 4; nt++) {
            int col = bn * 128 + wn * 32 + nt * 8 + 2 * (lane & 3);
            float2 v0 = make_float2(acc[mt][nt][0], acc[mt][nt][1]);
            float2 v1 = make_float2(acc[mt][nt][2], acc[mt][nt][3]);
            *(float2*)(O + (size_t)m * NC + col)       = v0;
            *(float2*)(O + (size_t)(m + 8) * NC + col) = v1;
        }
    }
}

// ---------------------------------------------------------------------------
// Launch
// ---------------------------------------------------------------------------
extern "C" void kernel_launch(void* const* d_in, const int* in_sizes, int n_in,
                              void* d_out, int out_size) {
    const float* Q  = (const float*)d_in[0];   // [16384, 64]
    const float* Km = (const float*)d_in[1];   // [4096, 64]
    const float* V  = (const float*)d_in[2];   // [4096, 1024]
    float* out = (float*)d_out;                // [16384, 1024]
    float* P   = out + OUT_ELEMS;              // [16384, 4096] p_attn

    static bool attr_done = false;
    if (!attr_done) {
        cudaFuncSetAttribute(pv_kernel, cudaFuncAttributeMaxDynamicSharedMemorySize,
                             PV_SMEM);
        attr_done = true;
    }

    dim3 gA(NL / 128, NG / 128);
    score_kernel<<<gA, 256>>>(Q, Km, P);

    vsplit_kernel<<<dim3(NC / 32, NL / 32), 256>>>(V);

    softmax_kernel<<<NG, 256>>>(P);

    dim3 gC(NC / 128, NG / 128);               // 8 x 128
    pv_kernel<<<gC, 256, PV_SMEM>>>(out);
}

// round 6
// speedup vs baseline: 2.1686x; 1.0251x over previous
#include <cuda_runtime.h>
#include <cuda_bf16.h>
#include <math.h>
#include <stdint.h>

// Problem shape (fixed by the dataset)
#define NG 16384   // n_genes
#define NL 4096    // n_latent (softmax axis, GEMM-K)
#define DK 64      // d_k
#define NC 1024    // n_cells
#define OUT_ELEMS (NG * NC)

// ---------------------------------------------------------------------------
// bf16 hi/lo scratch (static device arrays: allocation-free scratch)
// ---------------------------------------------------------------------------
__device__ __nv_bfloat16 g_Phi[(size_t)NG * NL];   // 134 MB
__device__ __nv_bfloat16 g_Plo[(size_t)NG * NL];   // 134 MB
__device__ __nv_bfloat16 g_VhiT[(size_t)NC * NL];  // 8 MB   V^T hi  [n][k]
__device__ __nv_bfloat16 g_VloT[(size_t)NC * NL];  // 8 MB   V^T lo  [n][k]

__device__ __forceinline__ uint32_t smem_to_u32(const void* p) {
    uint32_t a;
    asm("{ .reg .u64 t; cvta.to.shared.u64 t, %1; cvt.u32.u64 %0, t; }" : "=r"(a) : "l"(p));
    return a;
}

// ---------------------------------------------------------------------------
// JAX threefry2x32 Gumbel noise, partitionable mode, key (0, 42)
// ---------------------------------------------------------------------------
__device__ __forceinline__ float gumbel_at(uint32_t e) {
    uint32_t x0 = 0u, x1 = e;
    const uint32_t ks1 = 42u;
    const uint32_t ks2 = 0x1BD11BDAu ^ 42u;
    x1 += ks1;
#define TFR(r) { x0 += x1; x1 = __funnelshift_l(x1, x1, (r)); x1 ^= x0; }
    TFR(13) TFR(15) TFR(26) TFR(6)
    x0 += ks1; x1 += ks2 + 1u;
    TFR(17) TFR(29) TFR(16) TFR(24)
    x0 += ks2; x1 += 2u;
    TFR(13) TFR(15) TFR(26) TFR(6)
    x1 += ks1 + 3u;
    TFR(17) TFR(29) TFR(16) TFR(24)
    x0 += ks1; x1 += ks2 + 4u;
    TFR(13) TFR(15) TFR(26) TFR(6)
    x0 += ks2; x1 += 5u;
#undef TFR
    uint32_t bits = x0 ^ x1;
    float f = __uint_as_float(0x3F800000u | (bits >> 9)) - 1.0f;
    // w = -log(u), u ~= f. t = 1 - f is EXACT in fp32 (24-bit grid).
    float t = 1.0f - f;
    // Series path (t < 0.105): -log(1-t) = t*(1 + t/2 + ... + t^6/7), rel err < 6e-8
    float poly = 1.0f / 7.0f;
    poly = fmaf(poly, t, 1.0f / 6.0f);
    poly = fmaf(poly, t, 0.2f);
    poly = fmaf(poly, t, 0.25f);
    poly = fmaf(poly, t, 1.0f / 3.0f);
    poly = fmaf(poly, t, 0.5f);
    poly = fmaf(poly, t, 1.0f);
    float w_ser = t * poly;
    // MUFU path (t >= 0.105 -> w >= 0.11, absolute MUFU error harmless)
    float w_muf = -__logf(f);
    float w = (t < 0.105f) ? w_ser : w_muf;
    w = (f > 0.0f) ? w : 87.33654475f;   // f==0 -> u = tiny = 2^-126
    return -__logf(w);
}

// ---------------------------------------------------------------------------
// Kernel A: S = (Q @ K^T)/8 + gumbel
// ---------------------------------------------------------------------------
__global__ __launch_bounds__(256)
void score_kernel(const float* __restrict__ Q, const float* __restrict__ Km,
                  float* __restrict__ S)
{
    __shared__ float As[16][132];
    __shared__ float Bs[16][132];
    const int bm = blockIdx.y, bn = blockIdx.x;
    const int tid = threadIdx.x;
    const int tx = tid & 15, ty = tid >> 4;

    float acc[8][8];
#pragma unroll
    for (int i = 0; i < 8; i++)
#pragma unroll
        for (int j = 0; j < 8; j++) acc[i][j] = 0.0f;

    for (int k0 = 0; k0 < DK; k0 += 16) {
#pragma unroll
        for (int p = 0; p < 2; p++) {
            int idx = tid * 2 + p;
            int row = idx >> 2;
            int c4  = idx & 3;
            float4 va = *(const float4*)(Q  + (size_t)(bm * 128 + row) * DK + k0 + c4 * 4);
            As[c4 * 4 + 0][row] = va.x; As[c4 * 4 + 1][row] = va.y;
            As[c4 * 4 + 2][row] = va.z; As[c4 * 4 + 3][row] = va.w;
            float4 vb = *(const float4*)(Km + (size_t)(bn * 128 + row) * DK + k0 + c4 * 4);
            Bs[c4 * 4 + 0][row] = vb.x; Bs[c4 * 4 + 1][row] = vb.y;
            Bs[c4 * 4 + 2][row] = vb.z; Bs[c4 * 4 + 3][row] = vb.w;
        }
        __syncthreads();
#pragma unroll
        for (int kk = 0; kk < 16; kk++) {
            float a[8], b[8];
            *(float4*)&a[0] = *(const float4*)&As[kk][ty * 8];
            *(float4*)&a[4] = *(const float4*)&As[kk][ty * 8 + 4];
            *(float4*)&b[0] = *(const float4*)&Bs[kk][tx * 8];
            *(float4*)&b[4] = *(const float4*)&Bs[kk][tx * 8 + 4];
#pragma unroll
            for (int i = 0; i < 8; i++)
#pragma unroll
                for (int j = 0; j < 8; j++)
                    acc[i][j] = fmaf(a[i], b[j], acc[i][j]);
        }
        __syncthreads();
    }

#pragma unroll
    for (int i = 0; i < 8; i++) {
        uint32_t m = bm * 128 + ty * 8 + i;
        uint32_t e0 = m * (uint32_t)NL + bn * 128 + tx * 8;
        float4 o0, o1;
        o0.x = acc[i][0] * 0.125f + gumbel_at(e0 + 0);
        o0.y = acc[i][1] * 0.125f + gumbel_at(e0 + 1);
        o0.z = acc[i][2] * 0.125f + gumbel_at(e0 + 2);
        o0.w = acc[i][3] * 0.125f + gumbel_at(e0 + 3);
        o1.x = acc[i][4] * 0.125f + gumbel_at(e0 + 4);
        o1.y = acc[i][5] * 0.125f + gumbel_at(e0 + 5);
        o1.z = acc[i][6] * 0.125f + gumbel_at(e0 + 6);
        o1.w = acc[i][7] * 0.125f + gumbel_at(e0 + 7);
        *(float4*)(S + e0)     = o0;
        *(float4*)(S + e0 + 4) = o1;
    }
}

// ---------------------------------------------------------------------------
// Kernel B: in-place row softmax + fused bf16 hi/lo split of P
// ---------------------------------------------------------------------------
__device__ __forceinline__ void split1(float x, __nv_bfloat16& h, __nv_bfloat16& l) {
    h = __float2bfloat16(x);
    l = __float2bfloat16(x - __bfloat162float(h));
}

__global__ __launch_bounds__(256)
void softmax_kernel(float* __restrict__ P)
{
    __shared__ float4 row4[NL / 4];
    __shared__ float red[8];
    const int r = blockIdx.x, t = threadIdx.x;
    float4* g = (float4*)(P + (size_t)r * NL);

    float mx = -INFINITY;
#pragma unroll
    for (int q = 0; q < 4; q++) {
        float4 v = g[t + 256 * q];
        row4[t + 256 * q] = v;
        mx = fmaxf(mx, fmaxf(fmaxf(v.x, v.y), fmaxf(v.z, v.w)));
    }
#pragma unroll
    for (int o = 16; o > 0; o >>= 1)
        mx = fmaxf(mx, __shfl_xor_sync(0xffffffffu, mx, o));
    if ((t & 31) == 0) red[t >> 5] = mx;
    __syncthreads();
    mx = red[0];
#pragma unroll
    for (int w = 1; w < 8; w++) mx = fmaxf(mx, red[w]);
    __syncthreads();

    float s = 0.0f;
#pragma unroll
    for (int q = 0; q < 4; q++) {
        float4 v = row4[t + 256 * q];
        v.x = __expf(v.x - mx); v.y = __expf(v.y - mx);
        v.z = __expf(v.z - mx); v.w = __expf(v.w - mx);
        row4[t + 256 * q] = v;
        s += (v.x + v.y) + (v.z + v.w);
    }
#pragma unroll
    for (int o = 16; o > 0; o >>= 1)
        s += __shfl_xor_sync(0xffffffffu, s, o);
    if ((t & 31) == 0) red[t >> 5] = s;
    __syncthreads();
    float tot = red[0];
#pragma unroll
    for (int w = 1; w < 8; w++) tot += red[w];
    float inv = 1.0f / tot;
    __syncthreads();

    uint2* ph = (uint2*)(g_Phi + (size_t)r * NL);
    uint2* pl = (uint2*)(g_Plo + (size_t)r * NL);
#pragma unroll
    for (int q = 0; q < 4; q++) {
        float4 v = row4[t + 256 * q];
        v.x *= inv; v.y *= inv; v.z *= inv; v.w *= inv;
        g[t + 256 * q] = v;
        __nv_bfloat16 hx, hy, hz, hw, lx, ly, lz, lw;
        split1(v.x, hx, lx); split1(v.y, hy, ly);
        split1(v.z, hz, lz); split1(v.w, hw, lw);
        __nv_bfloat162 h01 = __nv_bfloat162(hx, hy), h23 = __nv_bfloat162(hz, hw);
        __nv_bfloat162 l01 = __nv_bfloat162(lx, ly), l23 = __nv_bfloat162(lz, lw);
        uint2 hv, lv;
        hv.x = *(uint32_t*)&h01; hv.y = *(uint32_t*)&h23;
        lv.x = *(uint32_t*)&l01; lv.y = *(uint32_t*)&l23;
        ph[t + 256 * q] = hv;
        pl[t + 256 * q] = lv;
    }
}

// ---------------------------------------------------------------------------
// Kernel B2: transpose + bf16-split V:  V[k][n] -> V^T hi/lo [n][k]
// ---------------------------------------------------------------------------
__global__ __launch_bounds__(256)
void vsplit_kernel(const float* __restrict__ V)
{
    __shared__ float tile[32][33];
    const int n0 = blockIdx.x * 32, k0 = blockIdx.y * 32;
    const int tx = threadIdx.x & 31, ty = threadIdx.x >> 5;   // 32 x 8
#pragma unroll
    for (int i = 0; i < 32; i += 8)
        tile[ty + i][tx] = V[(size_t)(k0 + ty + i) * NC + n0 + tx];
    __syncthreads();
#pragma unroll
    for (int i = 0; i < 32; i += 8) {
        float f = tile[tx][ty + i];            // = V[k0+tx][n0+ty+i]
        __nv_bfloat16 h, l;
        split1(f, h, l);
        size_t o = (size_t)(n0 + ty + i) * NL + k0 + tx;
        g_VhiT[o] = h;
        g_VloT[o] = l;
    }
}

// ---------------------------------------------------------------------------
// Kernel C: out = P @ V via warp-level bf16 mma.sync, cp.async double-buffered
// ONE sync per chunk: wait(c) -> sync -> issue loads(c+1) -> compute(c).
// 3 products: Phi*Vhi + Phi*Vlo + Plo*Vhi, fp32 accum.
// CTA tile 128x128, 8 warps (2x4), warp tile 64x32, BK=32, 2 stages.
// ---------------------------------------------------------------------------
#define SP 40                     // smem row stride in bf16 (80B)
#define ARR_BYTES (128 * SP * 2)  // 10240 B per array per stage
#define STAGE_BYTES (4 * ARR_BYTES)
#define PV_SMEM (2 * STAGE_BYTES) // 81920 B

__device__ __forceinline__ void ldsm4(uint32_t* r, uint32_t addr) {
    asm volatile("ldmatrix.sync.aligned.m8n8.x4.shared.b16 {%0,%1,%2,%3}, [%4];"
                 : "=r"(r[0]), "=r"(r[1]), "=r"(r[2]), "=r"(r[3]) : "r"(addr));
}
__device__ __forceinline__ void mma_bf16(float* c, const uint32_t* a,
                                         uint32_t b0, uint32_t b1) {
    asm volatile("mma.sync.aligned.m16n8k16.row.col.f32.bf16.bf16.f32 "
                 "{%0,%1,%2,%3}, {%4,%5,%6,%7}, {%8,%9}, {%0,%1,%2,%3};"
                 : "+f"(c[0]), "+f"(c[1]), "+f"(c[2]), "+f"(c[3])
                 : "r"(a[0]), "r"(a[1]), "r"(a[2]), "r"(a[3]), "r"(b0), "r"(b1));
}
__device__ __forceinline__ void cpa16(uint32_t dst, const void* src) {
    asm volatile("cp.async.cg.shared.global [%0], [%1], 16;" :: "r"(dst), "l"(src));
}
#define CP_COMMIT() asm volatile("cp.async.commit_group;" ::: "memory")
#define CP_WAIT0()  asm volatile("cp.async.wait_group 0;" ::: "memory")

__global__ __launch_bounds__(256, 2)
void pv_kernel(float* __restrict__ O)
{
    extern __shared__ __align__(16) char dsm[];
    const uint32_t sbase = smem_to_u32(dsm);

    const int tid = threadIdx.x;
    const int lane = tid & 31, wid = tid >> 5;
    const int wm = wid >> 2, wn = wid & 3;           // warp grid 2 x 4
    const int bn = blockIdx.x, bm = blockIdx.y;

    const __nv_bfloat16* srcs[4] = {
        g_Phi  + (size_t)(bm * 128) * NL,
        g_Plo  + (size_t)(bm * 128) * NL,
        g_VhiT + (size_t)(bn * 128) * NL,
        g_VloT + (size_t)(bn * 128) * NL
    };

    float acc[4][4][4];
#pragma unroll
    for (int i = 0; i < 4; i++)
#pragma unroll
        for (int j = 0; j < 4; j++)
#pragma unroll
            for (int q = 0; q < 4; q++) acc[i][j][q] = 0.0f;

    const int lrow = (lane & 7) + ((lane >> 3) & 1) * 8;   // 0..15
    const int lcol8 = (lane >> 4) * 8;                     // 0 or 8

    auto load_stage = [&](int st, int k0) {
        uint32_t stb = sbase + st * STAGE_BYTES;
#pragma unroll
        for (int a = 0; a < 4; a++)
#pragma unroll
            for (int u = 0; u < 2; u++) {
                int idx = tid + 256 * u;           // 0..511: 128 rows x 4 kc
                int row = idx >> 2, kc = idx & 3;
                uint32_t dst = stb + a * ARR_BYTES + (row * SP + kc * 8) * 2;
                cpa16(dst, srcs[a] + (size_t)row * NL + k0 + kc * 8);
            }
    };

    load_stage(0, 0);
    CP_COMMIT();

    const int NCH = NL / 32;   // 128 chunks
    for (int c = 0; c < NCH; c++) {
        CP_WAIT0();            // stage c data arrived
        __syncthreads();       // also: all reads of buffer (c+1)&1 (chunk c-1) done
        if (c + 1 < NCH) {
            load_stage((c + 1) & 1, (c + 1) * 32);
            CP_COMMIT();
        }

        const uint32_t stb = sbase + (c & 1) * STAGE_BYTES;
        const uint32_t uPhi = stb, uPlo = stb + ARR_BYTES;
        const uint32_t uVhi = stb + 2 * ARR_BYTES, uVlo = stb + 3 * ARR_BYTES;

#pragma unroll
        for (int kk = 0; kk < 32; kk += 16) {
            const uint32_t aoff = ((wm * 64 + lrow) * SP + kk + lcol8) * 2;
            const uint32_t boff = ((wn * 32 + lrow) * SP + kk + lcol8) * 2;
            uint32_t ah[4][4], al[4][4];
#pragma unroll
            for (int mt = 0; mt < 4; mt++) {
                ldsm4(ah[mt], uPhi + aoff + mt * (16 * SP * 2));
                ldsm4(al[mt], uPlo + aoff + mt * (16 * SP * 2));
            }
            uint32_t bh[2][4], bl[2][4];
#pragma unroll
            for (int np = 0; np < 2; np++) {
                ldsm4(bh[np], uVhi + boff + np * (16 * SP * 2));
                ldsm4(bl[np], uVlo + boff + np * (16 * SP * 2));
            }
#pragma unroll
            for (int mt = 0; mt < 4; mt++)
#pragma unroll
                for (int nt = 0; nt < 4; nt++) {
                    const int np = nt >> 1, sel = nt & 1;
                    mma_bf16(acc[mt][nt], ah[mt], bh[np][sel], bh[np][sel + 2]);
                    mma_bf16(acc[mt][nt], ah[mt], bl[np][sel], bl[np][sel + 2]);
                    mma_bf16(acc[mt][nt], al[mt], bh[np][sel], bh[np][sel + 2]);
                }
        }
    }

    // Epilogue
#pragma unroll
    for (int mt = 0; mt < 4; mt++) {
        int m = bm * 128 + wm * 64 + mt * 16 + (lane >> 2);
#pragma unroll
        for (int nt = 0; nt < 4; nt++) {
            int col = bn * 128 + wn * 32 + nt * 8 + 2 * (lane & 3);
            float2 v0 = make_float2(acc[mt][nt][0], acc[mt][nt][1]);
            float2 v1 = make_float2(acc[mt][nt][2], acc[mt][nt][3]);
            *(float2*)(O + (size_t)m * NC + col)       = v0;
            *(float2*)(O + (size_t)(m + 8) * NC + col) = v1;
        }
    }
}

// ---------------------------------------------------------------------------
// Launch
// ---------------------------------------------------------------------------
extern "C" void kernel_launch(void* const* d_in, const int* in_sizes, int n_in,
                              void* d_out, int out_size) {
    const float* Q  = (const float*)d_in[0];   // [16384, 64]
    const float* Km = (const float*)d_in[1];   // [4096, 64]
    const float* V  = (const float*)d_in[2];   // [4096, 1024]
    float* out = (float*)d_out;                // [16384, 1024]
    float* P   = out + OUT_ELEMS;              // [16384, 4096] p_attn

    static bool attr_done = false;
    if (!attr_done) {
        cudaFuncSetAttribute(pv_kernel, cudaFuncAttributeMaxDynamicSharedMemorySize,
                             PV_SMEM);
        attr_done = true;
    }

    dim3 gA(NL / 128, NG / 128);
    score_kernel<<<gA, 256>>>(Q, Km, P);

    vsplit_kernel<<<dim3(NC / 32, NL / 32), 256>>>(V);

    softmax_kernel<<<NG, 256>>>(P);

    dim3 gC(NC / 128, NG / 128);               // 8 x 128
    pv_kernel<<<gC, 256, PV_SMEM>>>(out);
}